// round 15
// baseline (speedup 1.0000x reference)
#include <cuda_runtime.h>
#include <math.h>
#include <stdint.h>

#define NTOK 16384
#define DIMV 1024
#define NH 4
#define HDV 256
#define EPSV 1e-5f
#define DEPTH_SCALE 0.40824829046386296f

// ---------------- scratch (device globals; no allocation) ----------------
__device__ __align__(16) float g_cat[(size_t)NH * NTOK * 512];     // [H][N][2HD]
__device__ __align__(16) float g_gamma[(size_t)NH * NTOK * HDV];   // [H][N][HD]
__device__ __align__(16) float g_dt[(size_t)NTOK * NH];            // [N][H]
__device__ __align__(16) float g_xvcat[(size_t)2 * NTOK * DIMV];   // x_cat then v_cat (tf32-rounded)
__device__ __align__(16) float g_wo[(size_t)2 * DIMV * DIMV];      // Wo_x, Wo_v tf32-rounded

// ---------------- tf32 helpers ----------------
__device__ __forceinline__ float tf32_rna(float x) {
    uint32_t u;
    asm("cvt.rna.tf32.f32 %0, %1;" : "=r"(u) : "f"(x));
    return __uint_as_float(u);
}

__device__ __forceinline__ void mma_tf32(float* d, const float* a, const float* b) {
    asm volatile(
        "mma.sync.aligned.m16n8k8.row.col.f32.tf32.tf32.f32 "
        "{%0,%1,%2,%3}, {%4,%5,%6,%7}, {%8,%9}, {%0,%1,%2,%3};\n"
        : "+f"(d[0]), "+f"(d[1]), "+f"(d[2]), "+f"(d[3])
        : "r"(__float_as_uint(a[0])), "r"(__float_as_uint(a[1])),
          "r"(__float_as_uint(a[2])), "r"(__float_as_uint(a[3])),
          "r"(__float_as_uint(b[0])), "r"(__float_as_uint(b[1])));
}

__device__ __forceinline__ void cp16(void* smem, const void* g) {
    uint32_t s = (uint32_t)__cvta_generic_to_shared(smem);
    asm volatile("cp.async.cg.shared.global [%0], [%1], 16;\n" :: "r"(s), "l"(g));
}
#define CP_COMMIT() asm volatile("cp.async.commit_group;\n" ::)
#define CP_WAIT1()  asm volatile("cp.async.wait_group 1;\n" ::)

// =========================================================================
// K0: round Wo_x and Wo_v to tf32 (RNA) into contiguous g_wo — ONE launch
// =========================================================================
__global__ __launch_bounds__(256) void k0_round2(const float* __restrict__ srcA,
                                                 const float* __restrict__ srcB,
                                                 float* __restrict__ dst, int n4half)
{
    int i = blockIdx.x * 256 + threadIdx.x;
    if (i < n4half) {
        float4 a = *(const float4*)(srcA + (size_t)i * 4);
        a.x = tf32_rna(a.x); a.y = tf32_rna(a.y);
        a.z = tf32_rna(a.z); a.w = tf32_rna(a.w);
        *(float4*)(dst + (size_t)i * 4) = a;
        float4 b = *(const float4*)(srcB + (size_t)i * 4);
        b.x = tf32_rna(b.x); b.y = tf32_rna(b.y);
        b.z = tf32_rna(b.z); b.w = tf32_rna(b.w);
        *(float4*)(dst + (size_t)n4half * 4 + (size_t)i * 4) = b;
    }
}

// =========================================================================
// K1: LayerNorm + gate (R4-proven block-per-token form)
// =========================================================================
__global__ __launch_bounds__(256) void k1_ln_gate(
    const float* __restrict__ x, const float* __restrict__ v,
    const float* __restrict__ lxg, const float* __restrict__ lxb,
    const float* __restrict__ lvg, const float* __restrict__ lvb,
    const float* __restrict__ gw, const float* __restrict__ gb,
    const float* __restrict__ dtp)
{
    size_t tok = blockIdx.x;
    int tid = threadIdx.x, lane = tid & 31, w = tid >> 5;

    const float4 x4 = *(const float4*)(x + tok * DIMV + tid * 4);
    const float4 v4 = *(const float4*)(v + tok * DIMV + tid * 4);

    float sx  = x4.x + x4.y + x4.z + x4.w;
    float sxx = x4.x*x4.x + x4.y*x4.y + x4.z*x4.z + x4.w*x4.w;
    float sv  = v4.x + v4.y + v4.z + v4.w;
    float svv = v4.x*v4.x + v4.y*v4.y + v4.z*v4.z + v4.w*v4.w;
    #pragma unroll
    for (int o = 16; o; o >>= 1) {
        sx  += __shfl_xor_sync(0xffffffffu, sx,  o);
        sxx += __shfl_xor_sync(0xffffffffu, sxx, o);
        sv  += __shfl_xor_sync(0xffffffffu, sv,  o);
        svv += __shfl_xor_sync(0xffffffffu, svv, o);
    }
    __shared__ float4 red[8];
    if (lane == 0) red[w] = make_float4(sx, sxx, sv, svv);
    __syncthreads();
    float tsx = 0.f, tsxx = 0.f, tsv = 0.f, tsvv = 0.f;
    #pragma unroll
    for (int i = 0; i < 8; i++) {
        float4 r = red[i];
        tsx += r.x; tsxx += r.y; tsv += r.z; tsvv += r.w;
    }
    const float inv = 1.0f / DIMV;
    float mux = tsx * inv, varx = tsxx * inv - mux * mux;
    float muv = tsv * inv, varv = tsvv * inv - muv * muv;
    float rsx = rsqrtf(varx + EPSV);
    float rsv = rsqrtf(varv + EPSV);

    int d0 = tid * 4;
    const float4 gxp = *(const float4*)(lxg + d0);
    const float4 bxp = *(const float4*)(lxb + d0);
    const float4 gvp = *(const float4*)(lvg + d0);
    const float4 bvp = *(const float4*)(lvb + d0);

    float4 xn, vn;
    xn.x = (x4.x - mux) * rsx * gxp.x + bxp.x;
    xn.y = (x4.y - mux) * rsx * gxp.y + bxp.y;
    xn.z = (x4.z - mux) * rsx * gxp.z + bxp.z;
    xn.w = (x4.w - mux) * rsx * gxp.w + bxp.w;
    vn.x = (v4.x - muv) * rsv * gvp.x + bvp.x;
    vn.y = (v4.y - muv) * rsv * gvp.y + bvp.y;
    vn.z = (v4.z - muv) * rsv * gvp.z + bvp.z;
    vn.w = (v4.w - muv) * rsv * gvp.w + bvp.w;

    int h = tid >> 6;
    int c = (tid & 63) * 4;
    size_t base = ((size_t)h * NTOK + tok) * 512;
    *(float4*)(g_cat + base + c)       = xn;
    *(float4*)(g_cat + base + 256 + c) = vn;

    const float4 gwx = *(const float4*)(gw + h * 512 + c);
    const float4 gwv = *(const float4*)(gw + h * 512 + 256 + c);
    float gp = xn.x*gwx.x + xn.y*gwx.y + xn.z*gwx.z + xn.w*gwx.w
             + vn.x*gwv.x + vn.y*gwv.y + vn.z*gwv.z + vn.w*gwv.w;
    #pragma unroll
    for (int o = 16; o; o >>= 1) gp += __shfl_xor_sync(0xffffffffu, gp, o);
    __shared__ float gsh[8];
    if (lane == 0) gsh[w] = gp;
    __syncthreads();
    if (tid < NH) {
        float logit = gsh[2 * tid] + gsh[2 * tid + 1] + gb[tid];
        float gate = 1.0f / (1.0f + expf(-logit));
        float sp = log1pf(expf(dtp[tid]));
        g_dt[tok * NH + tid] = 2.0f * sp * gate;
    }
}

// =========================================================================
// tf32 tensor-core GEMM: 128x128x32 block (R11-proven), dynamic smem.
// epi==0: C = sigmoid(A@B + bias[col]), bias = auxA + z*sAux
// epi==1: C = aux + scale*(A@B),        aux  = (z==0 ? auxA : auxB)
// =========================================================================
#define GBM 128
#define GBN 128
#define GBK 32
#define AS_STRIDE 36
#define BS_STRIDE 136
#define A_ST_FLOATS (GBM * AS_STRIDE)
#define B_ST_FLOATS (GBK * BS_STRIDE)
#define GEMM_SMEM_BYTES (2 * (A_ST_FLOATS + B_ST_FLOATS) * 4)

#define ASM(s,r,k) Asm[(s)*A_ST_FLOATS + (r)*AS_STRIDE + (k)]
#define BSM(s,r,c) Bsm[(s)*B_ST_FLOATS + (r)*BS_STRIDE + (c)]

__global__ __launch_bounds__(256) void tgemm_tf32(
    const float* __restrict__ Ag, const float* __restrict__ Bg,
    const float* __restrict__ auxA, const float* __restrict__ auxB,
    float* __restrict__ Cg,
    int M, int N, int K,
    long long sA, long long sB, long long sAux, long long sC,
    int epi, float scale)
{
    const int z = blockIdx.z;
    const float* A = Ag + (size_t)z * sA;
    const float* B = Bg + (size_t)z * sB;
    const float* AX = (epi == 0) ? (auxA + (size_t)z * sAux)
                                 : (z ? auxB : auxA);
    float* C = Cg + (size_t)z * sC;

    extern __shared__ float smp[];
    float* Asm = smp;
    float* Bsm = smp + 2 * A_ST_FLOATS;

    const int tid = threadIdx.x;
    const int lane = tid & 31, w = tid >> 5;
    const int bx = blockIdx.x, by = blockIdx.y;

    const int wm = (w & 3) * 32;
    const int wn = (w >> 2) * 64;
    const int g  = lane >> 2;
    const int t4 = lane & 3;

    const int ar[4] = { tid >> 3, (tid + 256) >> 3, (tid + 512) >> 3, (tid + 768) >> 3 };
    const int ak = (tid & 7) * 4;
    const int br[4] = { tid >> 5, (tid + 256) >> 5, (tid + 512) >> 5, (tid + 768) >> 5 };
    const int bc = (tid & 31) * 4;

    const float* Ab = A + (size_t)(by * GBM) * K;
    const float* Bb = B + bx * GBN;

    const int KT = K / GBK;

    #define ISSUE(slot, ktile) do {                                              \
        int _k0 = (ktile) * GBK;                                                 \
        _Pragma("unroll")                                                        \
        for (int q = 0; q < 4; q++) {                                            \
            cp16(&ASM(slot, ar[q], ak), Ab + (size_t)ar[q] * K + _k0 + ak);      \
            cp16(&BSM(slot, br[q], bc), Bb + (size_t)(_k0 + br[q]) * N + bc);    \
        }                                                                        \
        CP_COMMIT();                                                             \
    } while (0)

    float acc[2][8][4];
    #pragma unroll
    for (int mt = 0; mt < 2; mt++)
        #pragma unroll
        for (int nt = 0; nt < 8; nt++)
            #pragma unroll
            for (int i = 0; i < 4; i++) acc[mt][nt][i] = 0.f;

    ISSUE(0, 0);

    for (int kt = 0; kt < KT; kt++) {
        const int s = kt & 1;
        if (kt + 1 < KT) {
            ISSUE((kt + 1) & 1, kt + 1);
        } else {
            CP_COMMIT();
        }
        CP_WAIT1();
        __syncthreads();

        #pragma unroll
        for (int kk = 0; kk < GBK; kk += 8) {
            float a[2][4];
            #pragma unroll
            for (int mt = 0; mt < 2; mt++) {
                int r0 = wm + mt * 16 + g;
                a[mt][0] = ASM(s, r0,     kk + t4);
                a[mt][1] = ASM(s, r0 + 8, kk + t4);
                a[mt][2] = ASM(s, r0,     kk + t4 + 4);
                a[mt][3] = ASM(s, r0 + 8, kk + t4 + 4);
            }
            float b[8][2];
            #pragma unroll
            for (int nt = 0; nt < 8; nt++) {
                int c0 = wn + nt * 8 + g;
                b[nt][0] = BSM(s, kk + t4,     c0);
                b[nt][1] = BSM(s, kk + t4 + 4, c0);
            }
            #pragma unroll
            for (int mt = 0; mt < 2; mt++)
                #pragma unroll
                for (int nt = 0; nt < 8; nt++)
                    mma_tf32(acc[mt][nt], a[mt], b[nt]);
        }
        __syncthreads();
    }

    #pragma unroll
    for (int mt = 0; mt < 2; mt++) {
        int r0 = by * GBM + wm + mt * 16 + g;
        #pragma unroll
        for (int nt = 0; nt < 8; nt++) {
            int c = bx * GBN + wn + nt * 8 + t4 * 2;
            size_t idx0 = (size_t)r0 * N + c;
            size_t idx1 = (size_t)(r0 + 8) * N + c;
            float2 o0, o1;
            if (epi == 0) {
                float b0 = AX[c], b1 = AX[c + 1];
                o0.x = 1.0f / (1.0f + expf(-(acc[mt][nt][0] + b0)));
                o0.y = 1.0f / (1.0f + expf(-(acc[mt][nt][1] + b1)));
                o1.x = 1.0f / (1.0f + expf(-(acc[mt][nt][2] + b0)));
                o1.y = 1.0f / (1.0f + expf(-(acc[mt][nt][3] + b1)));
            } else {
                float2 r0v = *(const float2*)(AX + idx0);
                float2 r1v = *(const float2*)(AX + idx1);
                o0.x = r0v.x + scale * acc[mt][nt][0];
                o0.y = r0v.y + scale * acc[mt][nt][1];
                o1.x = r1v.x + scale * acc[mt][nt][2];
                o1.y = r1v.y + scale * acc[mt][nt][3];
            }
            *(float2*)(C + idx0) = o0;
            *(float2*)(C + idx1) = o1;
        }
    }
    #undef ISSUE
}

// =========================================================================
// K3: Christoffel + Heun — R11 register form, TOK3=32,
// EXPERIMENT: __launch_bounds__(256, 4) → ≤64 regs → 4 CTAs/SM.
// =========================================================================
#define TOK3 32

__device__ __forceinline__ float christoffel(
    float* sv, float* sx, float* st,
    float xq, float vq,
    const float Ur0[8], const float Ur1[8],
    const float Wr0[8], const float Wr1[8],
    const float vpr[16],
    int lane, int w, int tid)
{
    sv[tid] = vq;
    sx[tid] = xq;
    __syncthreads();
    float c0 = 0.f, c1 = 0.f, g0 = 0.f, g1 = 0.f;
    #pragma unroll
    for (int i = 0; i < 8; i++) {
        float vv = sv[lane + 32 * i];
        float xx = sx[lane + 32 * i];
        c0 += Ur0[i] * vv; c1 += Ur1[i] * vv;
        g0 += Wr0[i] * xx; g1 += Wr1[i] * xx;
    }
    #pragma unroll
    for (int o = 16; o; o >>= 1) {
        c0 += __shfl_xor_sync(0xffffffffu, c0, o);
        c1 += __shfl_xor_sync(0xffffffffu, c1, o);
        g0 += __shfl_xor_sync(0xffffffffu, g0, o);
        g1 += __shfl_xor_sync(0xffffffffu, g1, o);
    }
    if (lane == 0) {
        st[2 * w]     = c0 * c0 * tanhf(g0);
        st[2 * w + 1] = c1 * c1 * tanhf(g1);
    }
    __syncthreads();
    float gv = 0.f;
    #pragma unroll
    for (int r = 0; r < 16; r++) gv += vpr[r] * st[r];
    return gv;
}

__global__ __launch_bounds__(256, 4) void k3_heun(
    const float* __restrict__ F,
    const float* __restrict__ U, const float* __restrict__ Wx,
    const float* __restrict__ Vp)
{
    const int h = blockIdx.y;
    const int tid = threadIdx.x, lane = tid & 31, w = tid >> 5;

    __shared__ float sv[256], sx[256], st[16];

    float Ur0[8], Ur1[8], Wr0[8], Wr1[8];
    const int r0 = 2 * w;
    #pragma unroll
    for (int i = 0; i < 8; i++) {
        Ur0[i] = U[h * 4096 + r0 * 256 + lane + 32 * i];
        Ur1[i] = U[h * 4096 + (r0 + 1) * 256 + lane + 32 * i];
        Wr0[i] = Wx[h * 4096 + r0 * 256 + lane + 32 * i];
        Wr1[i] = Wx[h * 4096 + (r0 + 1) * 256 + lane + 32 * i];
    }
    float vpr[16];
    #pragma unroll
    for (int r = 0; r < 16; r++) vpr[r] = Vp[h * 4096 + tid * 16 + r];

    for (int t = 0; t < TOK3; t++) {
        size_t tok = (size_t)blockIdx.x * TOK3 + t;
        float dt = g_dt[tok * NH + h];
        size_t cb = ((size_t)h * NTOK + tok) * 512;
        float xh = g_cat[cb + tid];
        float vh = g_cat[cb + 256 + tid];
        float Fd = F[tok * DIMV + h * HDV + tid];
        float gm = g_gamma[((size_t)h * NTOK + tok) * HDV + tid];

        float gv1 = christoffel(sv, sx, st, xh, vh, Ur0, Ur1, Wr0, Wr1, vpr, lane, w, tid);
        float k1v = Fd - gv1 - gm * vh;
        float xe = xh + dt * vh;
        float ve = vh + dt * k1v;
        float gv2 = christoffel(sv, sx, st, xe, ve, Ur0, Ur1, Wr0, Wr1, vpr, lane, w, tid);
        float k2v = Fd - gv2 - gm * ve;

        float xnew = xh + dt * vh + 0.5f * dt * dt * k1v;
        float vnew = vh + 0.5f * dt * (k1v + k2v);
        g_xvcat[tok * DIMV + h * HDV + tid] = tf32_rna(xnew);
        g_xvcat[(size_t)NTOK * DIMV + tok * DIMV + h * HDV + tid] = tf32_rna(vnew);
    }
}

// =========================================================================
// launch — R13 structure (merged K0, per-token K1, merged K4)
// =========================================================================
extern "C" void kernel_launch(void* const* d_in, const int* in_sizes, int n_in,
                              void* d_out, int out_size)
{
    const float* x      = (const float*)d_in[0];
    const float* v      = (const float*)d_in[1];
    const float* F      = (const float*)d_in[2];
    const float* ln_x_g = (const float*)d_in[3];
    const float* ln_x_b = (const float*)d_in[4];
    const float* ln_v_g = (const float*)d_in[5];
    const float* ln_v_b = (const float*)d_in[6];
    const float* U      = (const float*)d_in[7];
    const float* Wx     = (const float*)d_in[8];
    const float* Vp     = (const float*)d_in[9];
    const float* gate_w = (const float*)d_in[10];
    const float* gate_b = (const float*)d_in[11];
    const float* fric_w = (const float*)d_in[12];
    const float* fric_b = (const float*)d_in[13];
    const float* dt_p   = (const float*)d_in[14];
    const float* Wo_x   = (const float*)d_in[15];
    const float* Wo_v   = (const float*)d_in[16];
    float* out = (float*)d_out;

    float *cat, *gamma, *xvcat, *wo;
    cudaGetSymbolAddress((void**)&cat,   g_cat);
    cudaGetSymbolAddress((void**)&gamma, g_gamma);
    cudaGetSymbolAddress((void**)&xvcat, g_xvcat);
    cudaGetSymbolAddress((void**)&wo,    g_wo);

    cudaFuncSetAttribute(tgemm_tf32,
                         cudaFuncAttributeMaxDynamicSharedMemorySize,
                         GEMM_SMEM_BYTES);

    // (1) K0: round both Wo weights to tf32
    {
        int n4h = DIMV * DIMV / 4;
        k0_round2<<<(n4h + 255) / 256, 256>>>(Wo_x, Wo_v, wo, n4h);
    }

    // (2) K1: LN + gate/dt + cat (block-per-token)
    k1_ln_gate<<<NTOK, 256>>>(x, v, ln_x_g, ln_x_b, ln_v_g, ln_v_b,
                              gate_w, gate_b, dt_p);

    // (3) K2: friction gamma per head
    {
        dim3 grid(HDV / GBN, NTOK / GBM, NH);   // (2, 128, 4)
        tgemm_tf32<<<grid, 256, GEMM_SMEM_BYTES>>>(cat, fric_w, fric_b,
                                  (const float*)0, gamma,
                                  NTOK, HDV, 2 * HDV,
                                  (long long)NTOK * 512, (long long)512 * HDV,
                                  (long long)HDV, (long long)NTOK * HDV,
                                  0, 0.0f);
    }

    // (4) K3: Christoffel + Heun (register form, TOK3=32, 4 CTAs/SM)
    {
        dim3 grid(NTOK / TOK3, NH);   // (512, 4)
        k3_heun<<<grid, 256>>>(F, U, Wx, Vp);
    }

    // (5) K4: both output projections in ONE launch (grid.z = 2)
    {
        dim3 grid(DIMV / GBN, NTOK / GBM, 2);   // (8, 128, 2)
        tgemm_tf32<<<grid, 256, GEMM_SMEM_BYTES>>>(xvcat, wo, x, v, out,
                                  NTOK, DIMV, DIMV,
                                  (long long)NTOK * DIMV,
                                  (long long)DIMV * DIMV,
                                  0,
                                  (long long)NTOK * DIMV,
                                  1, DEPTH_SCALE);
    }
}

// round 16
// speedup vs baseline: 1.1865x; 1.1865x over previous
#include <cuda_runtime.h>
#include <math.h>
#include <stdint.h>

#define NTOK 16384
#define DIMV 1024
#define NH 4
#define HDV 256
#define EPSV 1e-5f
#define DEPTH_SCALE 0.40824829046386296f

// ---------------- scratch (device globals; no allocation) ----------------
__device__ __align__(16) float g_cat[(size_t)NH * NTOK * 512];     // [H][N][2HD]
__device__ __align__(16) float g_gamma[(size_t)NH * NTOK * HDV];   // [H][N][HD]
__device__ __align__(16) float g_dt[(size_t)NTOK * NH];            // [N][H]
__device__ __align__(16) float g_xvcat[(size_t)2 * NTOK * DIMV];   // x_cat then v_cat (tf32-rounded)
__device__ __align__(16) float g_wo[(size_t)2 * DIMV * DIMV];      // Wo_x, Wo_v tf32-rounded

// ---------------- tf32 helpers ----------------
__device__ __forceinline__ float tf32_rna(float x) {
    uint32_t u;
    asm("cvt.rna.tf32.f32 %0, %1;" : "=r"(u) : "f"(x));
    return __uint_as_float(u);
}

__device__ __forceinline__ void mma_tf32(float* d, const float* a, const float* b) {
    asm volatile(
        "mma.sync.aligned.m16n8k8.row.col.f32.tf32.tf32.f32 "
        "{%0,%1,%2,%3}, {%4,%5,%6,%7}, {%8,%9}, {%0,%1,%2,%3};\n"
        : "+f"(d[0]), "+f"(d[1]), "+f"(d[2]), "+f"(d[3])
        : "r"(__float_as_uint(a[0])), "r"(__float_as_uint(a[1])),
          "r"(__float_as_uint(a[2])), "r"(__float_as_uint(a[3])),
          "r"(__float_as_uint(b[0])), "r"(__float_as_uint(b[1])));
}

__device__ __forceinline__ void cp16(void* smem, const void* g) {
    uint32_t s = (uint32_t)__cvta_generic_to_shared(smem);
    asm volatile("cp.async.cg.shared.global [%0], [%1], 16;\n" :: "r"(s), "l"(g));
}
#define CP_COMMIT() asm volatile("cp.async.commit_group;\n" ::)
#define CP_WAIT1()  asm volatile("cp.async.wait_group 1;\n" ::)

// =========================================================================
// K0: round Wo_x and Wo_v to tf32 (RNA) into contiguous g_wo — ONE launch
// =========================================================================
__global__ __launch_bounds__(256) void k0_round2(const float* __restrict__ srcA,
                                                 const float* __restrict__ srcB,
                                                 float* __restrict__ dst, int n4half)
{
    int i = blockIdx.x * 256 + threadIdx.x;
    if (i < n4half) {
        float4 a = *(const float4*)(srcA + (size_t)i * 4);
        a.x = tf32_rna(a.x); a.y = tf32_rna(a.y);
        a.z = tf32_rna(a.z); a.w = tf32_rna(a.w);
        *(float4*)(dst + (size_t)i * 4) = a;
        float4 b = *(const float4*)(srcB + (size_t)i * 4);
        b.x = tf32_rna(b.x); b.y = tf32_rna(b.y);
        b.z = tf32_rna(b.z); b.w = tf32_rna(b.w);
        *(float4*)(dst + (size_t)n4half * 4 + (size_t)i * 4) = b;
    }
}

// =========================================================================
// K1 (EXPERIMENT): 128 threads per token. Each thread owns float4 chunks
// fi0=tid and fi1=tid+128. 4-warp smem reduce instead of 8.
// =========================================================================
__global__ __launch_bounds__(128) void k1_ln_gate(
    const float* __restrict__ x, const float* __restrict__ v,
    const float* __restrict__ lxg, const float* __restrict__ lxb,
    const float* __restrict__ lvg, const float* __restrict__ lvb,
    const float* __restrict__ gw, const float* __restrict__ gb,
    const float* __restrict__ dtp)
{
    const size_t tok = blockIdx.x;
    const int tid = threadIdx.x, lane = tid & 31, w = tid >> 5;
    const int fi0 = tid, fi1 = tid + 128;

    const float4 x40 = *(const float4*)(x + tok * DIMV + fi0 * 4);
    const float4 x41 = *(const float4*)(x + tok * DIMV + fi1 * 4);
    const float4 v40 = *(const float4*)(v + tok * DIMV + fi0 * 4);
    const float4 v41 = *(const float4*)(v + tok * DIMV + fi1 * 4);

    float sx  = x40.x + x40.y + x40.z + x40.w + x41.x + x41.y + x41.z + x41.w;
    float sxx = x40.x*x40.x + x40.y*x40.y + x40.z*x40.z + x40.w*x40.w
              + x41.x*x41.x + x41.y*x41.y + x41.z*x41.z + x41.w*x41.w;
    float sv  = v40.x + v40.y + v40.z + v40.w + v41.x + v41.y + v41.z + v41.w;
    float svv = v40.x*v40.x + v40.y*v40.y + v40.z*v40.z + v40.w*v40.w
              + v41.x*v41.x + v41.y*v41.y + v41.z*v41.z + v41.w*v41.w;
    #pragma unroll
    for (int o = 16; o; o >>= 1) {
        sx  += __shfl_xor_sync(0xffffffffu, sx,  o);
        sxx += __shfl_xor_sync(0xffffffffu, sxx, o);
        sv  += __shfl_xor_sync(0xffffffffu, sv,  o);
        svv += __shfl_xor_sync(0xffffffffu, svv, o);
    }
    __shared__ float4 red[4];
    if (lane == 0) red[w] = make_float4(sx, sxx, sv, svv);
    __syncthreads();
    float tsx = 0.f, tsxx = 0.f, tsv = 0.f, tsvv = 0.f;
    #pragma unroll
    for (int i = 0; i < 4; i++) {
        float4 r = red[i];
        tsx += r.x; tsxx += r.y; tsv += r.z; tsvv += r.w;
    }
    const float inv = 1.0f / DIMV;
    const float mux = tsx * inv, varx = tsxx * inv - mux * mux;
    const float muv = tsv * inv, varv = tsvv * inv - muv * muv;
    const float rsx = rsqrtf(varx + EPSV);
    const float rsv = rsqrtf(varv + EPSV);

    // chunk 0
    const int h0 = fi0 >> 6, c0 = (fi0 & 63) * 4;
    const int h1 = fi1 >> 6, c1 = (fi1 & 63) * 4;

    const float4 gxp0 = *(const float4*)(lxg + fi0 * 4);
    const float4 bxp0 = *(const float4*)(lxb + fi0 * 4);
    const float4 gvp0 = *(const float4*)(lvg + fi0 * 4);
    const float4 bvp0 = *(const float4*)(lvb + fi0 * 4);
    const float4 gxp1 = *(const float4*)(lxg + fi1 * 4);
    const float4 bxp1 = *(const float4*)(lxb + fi1 * 4);
    const float4 gvp1 = *(const float4*)(lvg + fi1 * 4);
    const float4 bvp1 = *(const float4*)(lvb + fi1 * 4);

    float4 xn0, vn0, xn1, vn1;
    xn0.x = (x40.x - mux) * rsx * gxp0.x + bxp0.x;
    xn0.y = (x40.y - mux) * rsx * gxp0.y + bxp0.y;
    xn0.z = (x40.z - mux) * rsx * gxp0.z + bxp0.z;
    xn0.w = (x40.w - mux) * rsx * gxp0.w + bxp0.w;
    vn0.x = (v40.x - muv) * rsv * gvp0.x + bvp0.x;
    vn0.y = (v40.y - muv) * rsv * gvp0.y + bvp0.y;
    vn0.z = (v40.z - muv) * rsv * gvp0.z + bvp0.z;
    vn0.w = (v40.w - muv) * rsv * gvp0.w + bvp0.w;
    xn1.x = (x41.x - mux) * rsx * gxp1.x + bxp1.x;
    xn1.y = (x41.y - mux) * rsx * gxp1.y + bxp1.y;
    xn1.z = (x41.z - mux) * rsx * gxp1.z + bxp1.z;
    xn1.w = (x41.w - mux) * rsx * gxp1.w + bxp1.w;
    vn1.x = (v41.x - muv) * rsv * gvp1.x + bvp1.x;
    vn1.y = (v41.y - muv) * rsv * gvp1.y + bvp1.y;
    vn1.z = (v41.z - muv) * rsv * gvp1.z + bvp1.z;
    vn1.w = (v41.w - muv) * rsv * gvp1.w + bvp1.w;

    size_t base0 = ((size_t)h0 * NTOK + tok) * 512;
    size_t base1 = ((size_t)h1 * NTOK + tok) * 512;
    *(float4*)(g_cat + base0 + c0)       = xn0;
    *(float4*)(g_cat + base0 + 256 + c0) = vn0;
    *(float4*)(g_cat + base1 + c1)       = xn1;
    *(float4*)(g_cat + base1 + 256 + c1) = vn1;

    // gate partials: warp w -> head w/2 via chunk0, head 2+w/2 via chunk1
    const float4 gwx0 = *(const float4*)(gw + h0 * 512 + c0);
    const float4 gwv0 = *(const float4*)(gw + h0 * 512 + 256 + c0);
    const float4 gwx1 = *(const float4*)(gw + h1 * 512 + c1);
    const float4 gwv1 = *(const float4*)(gw + h1 * 512 + 256 + c1);
    float gp0 = xn0.x*gwx0.x + xn0.y*gwx0.y + xn0.z*gwx0.z + xn0.w*gwx0.w
              + vn0.x*gwv0.x + vn0.y*gwv0.y + vn0.z*gwv0.z + vn0.w*gwv0.w;
    float gp1 = xn1.x*gwx1.x + xn1.y*gwx1.y + xn1.z*gwx1.z + xn1.w*gwx1.w
              + vn1.x*gwv1.x + vn1.y*gwv1.y + vn1.z*gwv1.z + vn1.w*gwv1.w;
    #pragma unroll
    for (int o = 16; o; o >>= 1) {
        gp0 += __shfl_xor_sync(0xffffffffu, gp0, o);
        gp1 += __shfl_xor_sync(0xffffffffu, gp1, o);
    }
    __shared__ float gshA[4], gshB[4];
    if (lane == 0) { gshA[w] = gp0; gshB[w] = gp1; }
    __syncthreads();
    if (tid < NH) {
        // head h: h<2 -> gshA[2h]+gshA[2h+1]; h>=2 -> gshB[2(h-2)]+gshB[2(h-2)+1]
        float p = (tid < 2) ? (gshA[2 * tid] + gshA[2 * tid + 1])
                            : (gshB[2 * (tid - 2)] + gshB[2 * (tid - 2) + 1]);
        float logit = p + gb[tid];
        float gate = 1.0f / (1.0f + expf(-logit));
        float sp = log1pf(expf(dtp[tid]));
        g_dt[tok * NH + tid] = 2.0f * sp * gate;
    }
}

// =========================================================================
// tf32 tensor-core GEMM: 128x128x32 block (R11-proven), dynamic smem.
// epi==0: C = sigmoid(A@B + bias[col]), bias = auxA + z*sAux
// epi==1: C = aux + scale*(A@B),        aux  = (z==0 ? auxA : auxB)
// =========================================================================
#define GBM 128
#define GBN 128
#define GBK 32
#define AS_STRIDE 36
#define BS_STRIDE 136
#define A_ST_FLOATS (GBM * AS_STRIDE)
#define B_ST_FLOATS (GBK * BS_STRIDE)
#define GEMM_SMEM_BYTES (2 * (A_ST_FLOATS + B_ST_FLOATS) * 4)

#define ASM(s,r,k) Asm[(s)*A_ST_FLOATS + (r)*AS_STRIDE + (k)]
#define BSM(s,r,c) Bsm[(s)*B_ST_FLOATS + (r)*BS_STRIDE + (c)]

__global__ __launch_bounds__(256) void tgemm_tf32(
    const float* __restrict__ Ag, const float* __restrict__ Bg,
    const float* __restrict__ auxA, const float* __restrict__ auxB,
    float* __restrict__ Cg,
    int M, int N, int K,
    long long sA, long long sB, long long sAux, long long sC,
    int epi, float scale)
{
    const int z = blockIdx.z;
    const float* A = Ag + (size_t)z * sA;
    const float* B = Bg + (size_t)z * sB;
    const float* AX = (epi == 0) ? (auxA + (size_t)z * sAux)
                                 : (z ? auxB : auxA);
    float* C = Cg + (size_t)z * sC;

    extern __shared__ float smp[];
    float* Asm = smp;
    float* Bsm = smp + 2 * A_ST_FLOATS;

    const int tid = threadIdx.x;
    const int lane = tid & 31, w = tid >> 5;
    const int bx = blockIdx.x, by = blockIdx.y;

    const int wm = (w & 3) * 32;
    const int wn = (w >> 2) * 64;
    const int g  = lane >> 2;
    const int t4 = lane & 3;

    const int ar[4] = { tid >> 3, (tid + 256) >> 3, (tid + 512) >> 3, (tid + 768) >> 3 };
    const int ak = (tid & 7) * 4;
    const int br[4] = { tid >> 5, (tid + 256) >> 5, (tid + 512) >> 5, (tid + 768) >> 5 };
    const int bc = (tid & 31) * 4;

    const float* Ab = A + (size_t)(by * GBM) * K;
    const float* Bb = B + bx * GBN;

    const int KT = K / GBK;

    #define ISSUE(slot, ktile) do {                                              \
        int _k0 = (ktile) * GBK;                                                 \
        _Pragma("unroll")                                                        \
        for (int q = 0; q < 4; q++) {                                            \
            cp16(&ASM(slot, ar[q], ak), Ab + (size_t)ar[q] * K + _k0 + ak);      \
            cp16(&BSM(slot, br[q], bc), Bb + (size_t)(_k0 + br[q]) * N + bc);    \
        }                                                                        \
        CP_COMMIT();                                                             \
    } while (0)

    float acc[2][8][4];
    #pragma unroll
    for (int mt = 0; mt < 2; mt++)
        #pragma unroll
        for (int nt = 0; nt < 8; nt++)
            #pragma unroll
            for (int i = 0; i < 4; i++) acc[mt][nt][i] = 0.f;

    ISSUE(0, 0);

    for (int kt = 0; kt < KT; kt++) {
        const int s = kt & 1;
        if (kt + 1 < KT) {
            ISSUE((kt + 1) & 1, kt + 1);
        } else {
            CP_COMMIT();
        }
        CP_WAIT1();
        __syncthreads();

        #pragma unroll
        for (int kk = 0; kk < GBK; kk += 8) {
            float a[2][4];
            #pragma unroll
            for (int mt = 0; mt < 2; mt++) {
                int r0 = wm + mt * 16 + g;
                a[mt][0] = ASM(s, r0,     kk + t4);
                a[mt][1] = ASM(s, r0 + 8, kk + t4);
                a[mt][2] = ASM(s, r0,     kk + t4 + 4);
                a[mt][3] = ASM(s, r0 + 8, kk + t4 + 4);
            }
            float b[8][2];
            #pragma unroll
            for (int nt = 0; nt < 8; nt++) {
                int c0 = wn + nt * 8 + g;
                b[nt][0] = BSM(s, kk + t4,     c0);
                b[nt][1] = BSM(s, kk + t4 + 4, c0);
            }
            #pragma unroll
            for (int mt = 0; mt < 2; mt++)
                #pragma unroll
                for (int nt = 0; nt < 8; nt++)
                    mma_tf32(acc[mt][nt], a[mt], b[nt]);
        }
        __syncthreads();
    }

    #pragma unroll
    for (int mt = 0; mt < 2; mt++) {
        int r0 = by * GBM + wm + mt * 16 + g;
        #pragma unroll
        for (int nt = 0; nt < 8; nt++) {
            int c = bx * GBN + wn + nt * 8 + t4 * 2;
            size_t idx0 = (size_t)r0 * N + c;
            size_t idx1 = (size_t)(r0 + 8) * N + c;
            float2 o0, o1;
            if (epi == 0) {
                float b0 = AX[c], b1 = AX[c + 1];
                o0.x = 1.0f / (1.0f + expf(-(acc[mt][nt][0] + b0)));
                o0.y = 1.0f / (1.0f + expf(-(acc[mt][nt][1] + b1)));
                o1.x = 1.0f / (1.0f + expf(-(acc[mt][nt][2] + b0)));
                o1.y = 1.0f / (1.0f + expf(-(acc[mt][nt][3] + b1)));
            } else {
                float2 r0v = *(const float2*)(AX + idx0);
                float2 r1v = *(const float2*)(AX + idx1);
                o0.x = r0v.x + scale * acc[mt][nt][0];
                o0.y = r0v.y + scale * acc[mt][nt][1];
                o1.x = r1v.x + scale * acc[mt][nt][2];
                o1.y = r1v.y + scale * acc[mt][nt][3];
            }
            *(float2*)(C + idx0) = o0;
            *(float2*)(C + idx1) = o1;
        }
    }
    #undef ISSUE
}

// =========================================================================
// K3: Christoffel + Heun — R11/R13-proven register form, TOK3=32,
// NO launch bounds (regs=80, 3 CTAs/SM — measured optimum).
// =========================================================================
#define TOK3 32

__device__ __forceinline__ float christoffel(
    float* sv, float* sx, float* st,
    float xq, float vq,
    const float Ur0[8], const float Ur1[8],
    const float Wr0[8], const float Wr1[8],
    const float vpr[16],
    int lane, int w, int tid)
{
    sv[tid] = vq;
    sx[tid] = xq;
    __syncthreads();
    float c0 = 0.f, c1 = 0.f, g0 = 0.f, g1 = 0.f;
    #pragma unroll
    for (int i = 0; i < 8; i++) {
        float vv = sv[lane + 32 * i];
        float xx = sx[lane + 32 * i];
        c0 += Ur0[i] * vv; c1 += Ur1[i] * vv;
        g0 += Wr0[i] * xx; g1 += Wr1[i] * xx;
    }
    #pragma unroll
    for (int o = 16; o; o >>= 1) {
        c0 += __shfl_xor_sync(0xffffffffu, c0, o);
        c1 += __shfl_xor_sync(0xffffffffu, c1, o);
        g0 += __shfl_xor_sync(0xffffffffu, g0, o);
        g1 += __shfl_xor_sync(0xffffffffu, g1, o);
    }
    if (lane == 0) {
        st[2 * w]     = c0 * c0 * tanhf(g0);
        st[2 * w + 1] = c1 * c1 * tanhf(g1);
    }
    __syncthreads();
    float gv = 0.f;
    #pragma unroll
    for (int r = 0; r < 16; r++) gv += vpr[r] * st[r];
    return gv;
}

__global__ __launch_bounds__(256) void k3_heun(
    const float* __restrict__ F,
    const float* __restrict__ U, const float* __restrict__ Wx,
    const float* __restrict__ Vp)
{
    const int h = blockIdx.y;
    const int tid = threadIdx.x, lane = tid & 31, w = tid >> 5;

    __shared__ float sv[256], sx[256], st[16];

    float Ur0[8], Ur1[8], Wr0[8], Wr1[8];
    const int r0 = 2 * w;
    #pragma unroll
    for (int i = 0; i < 8; i++) {
        Ur0[i] = U[h * 4096 + r0 * 256 + lane + 32 * i];
        Ur1[i] = U[h * 4096 + (r0 + 1) * 256 + lane + 32 * i];
        Wr0[i] = Wx[h * 4096 + r0 * 256 + lane + 32 * i];
        Wr1[i] = Wx[h * 4096 + (r0 + 1) * 256 + lane + 32 * i];
    }
    float vpr[16];
    #pragma unroll
    for (int r = 0; r < 16; r++) vpr[r] = Vp[h * 4096 + tid * 16 + r];

    for (int t = 0; t < TOK3; t++) {
        size_t tok = (size_t)blockIdx.x * TOK3 + t;
        float dt = g_dt[tok * NH + h];
        size_t cb = ((size_t)h * NTOK + tok) * 512;
        float xh = g_cat[cb + tid];
        float vh = g_cat[cb + 256 + tid];
        float Fd = F[tok * DIMV + h * HDV + tid];
        float gm = g_gamma[((size_t)h * NTOK + tok) * HDV + tid];

        float gv1 = christoffel(sv, sx, st, xh, vh, Ur0, Ur1, Wr0, Wr1, vpr, lane, w, tid);
        float k1v = Fd - gv1 - gm * vh;
        float xe = xh + dt * vh;
        float ve = vh + dt * k1v;
        float gv2 = christoffel(sv, sx, st, xe, ve, Ur0, Ur1, Wr0, Wr1, vpr, lane, w, tid);
        float k2v = Fd - gv2 - gm * ve;

        float xnew = xh + dt * vh + 0.5f * dt * dt * k1v;
        float vnew = vh + 0.5f * dt * (k1v + k2v);
        g_xvcat[tok * DIMV + h * HDV + tid] = tf32_rna(xnew);
        g_xvcat[(size_t)NTOK * DIMV + tok * DIMV + h * HDV + tid] = tf32_rna(vnew);
    }
}

// =========================================================================
// launch — R13 champion structure (merged K0, merged K4)
// =========================================================================
extern "C" void kernel_launch(void* const* d_in, const int* in_sizes, int n_in,
                              void* d_out, int out_size)
{
    const float* x      = (const float*)d_in[0];
    const float* v      = (const float*)d_in[1];
    const float* F      = (const float*)d_in[2];
    const float* ln_x_g = (const float*)d_in[3];
    const float* ln_x_b = (const float*)d_in[4];
    const float* ln_v_g = (const float*)d_in[5];
    const float* ln_v_b = (const float*)d_in[6];
    const float* U      = (const float*)d_in[7];
    const float* Wx     = (const float*)d_in[8];
    const float* Vp     = (const float*)d_in[9];
    const float* gate_w = (const float*)d_in[10];
    const float* gate_b = (const float*)d_in[11];
    const float* fric_w = (const float*)d_in[12];
    const float* fric_b = (const float*)d_in[13];
    const float* dt_p   = (const float*)d_in[14];
    const float* Wo_x   = (const float*)d_in[15];
    const float* Wo_v   = (const float*)d_in[16];
    float* out = (float*)d_out;

    float *cat, *gamma, *xvcat, *wo;
    cudaGetSymbolAddress((void**)&cat,   g_cat);
    cudaGetSymbolAddress((void**)&gamma, g_gamma);
    cudaGetSymbolAddress((void**)&xvcat, g_xvcat);
    cudaGetSymbolAddress((void**)&wo,    g_wo);

    cudaFuncSetAttribute(tgemm_tf32,
                         cudaFuncAttributeMaxDynamicSharedMemorySize,
                         GEMM_SMEM_BYTES);

    // (1) K0: round both Wo weights to tf32
    {
        int n4h = DIMV * DIMV / 4;
        k0_round2<<<(n4h + 255) / 256, 256>>>(Wo_x, Wo_v, wo, n4h);
    }

    // (2) K1: LN + gate/dt + cat (128 threads per token — experiment)
    k1_ln_gate<<<NTOK, 128>>>(x, v, ln_x_g, ln_x_b, ln_v_g, ln_v_b,
                              gate_w, gate_b, dt_p);

    // (3) K2: friction gamma per head
    {
        dim3 grid(HDV / GBN, NTOK / GBM, NH);   // (2, 128, 4)
        tgemm_tf32<<<grid, 256, GEMM_SMEM_BYTES>>>(cat, fric_w, fric_b,
                                  (const float*)0, gamma,
                                  NTOK, HDV, 2 * HDV,
                                  (long long)NTOK * 512, (long long)512 * HDV,
                                  (long long)HDV, (long long)NTOK * HDV,
                                  0, 0.0f);
    }

    // (4) K3: Christoffel + Heun (register form, TOK3=32, no launch bounds)
    {
        dim3 grid(NTOK / TOK3, NH);   // (512, 4)
        k3_heun<<<grid, 256>>>(F, U, Wx, Vp);
    }

    // (5) K4: both output projections in ONE launch (grid.z = 2)
    {
        dim3 grid(DIMV / GBN, NTOK / GBM, 2);   // (8, 128, 2)
        tgemm_tf32<<<grid, 256, GEMM_SMEM_BYTES>>>(xvcat, wo, x, v, out,
                                  NTOK, DIMV, DIMV,
                                  (long long)NTOK * DIMV,
                                  (long long)DIMV * DIMV,
                                  0,
                                  (long long)NTOK * DIMV,
                                  1, DEPTH_SCALE);
    }
}